// round 4
// baseline (speedup 1.0000x reference)
#include <cuda_runtime.h>
#include <cstdint>
#include <math.h>

// Problem constants (shapes are fixed by the dataset)
#define BB 8
#define CC 64
#define NN 8192
#define MM 2048
#define KNNK 16
#define FPS_M 1433   // int(2048 * 0.7)
#define RAND_M 615   // 2048 - 1433

// ---------------------------------------------------------------------------
// Threefry-2x32 core (jax threefry2x32 primitive)
// ---------------------------------------------------------------------------
__host__ __device__ __forceinline__ void threefry2x32(
    uint32_t k0, uint32_t k1, uint32_t c0, uint32_t c1,
    uint32_t* o0, uint32_t* o1) {
  uint32_t ks2 = 0x1BD11BDAu ^ k0 ^ k1;
  uint32_t x0 = c0 + k0;
  uint32_t x1 = c1 + k1;
#define TF_ROTL(v, r) (((v) << (r)) | ((v) >> (32 - (r))))
#define TF_ROUND(r) do { x0 += x1; x1 = TF_ROTL(x1, r); x1 ^= x0; } while (0)
  TF_ROUND(13); TF_ROUND(15); TF_ROUND(26); TF_ROUND(6);
  x0 += k1; x1 += ks2 + 1u;
  TF_ROUND(17); TF_ROUND(29); TF_ROUND(16); TF_ROUND(24);
  x0 += ks2; x1 += k0 + 2u;
  TF_ROUND(13); TF_ROUND(15); TF_ROUND(26); TF_ROUND(6);
  x0 += k0; x1 += k1 + 3u;
  TF_ROUND(17); TF_ROUND(29); TF_ROUND(16); TF_ROUND(24);
  x0 += k1; x1 += ks2 + 4u;
  TF_ROUND(13); TF_ROUND(15); TF_ROUND(26); TF_ROUND(6);
  x0 += ks2; x1 += k0 + 5u;
#undef TF_ROUND
#undef TF_ROTL
  *o0 = x0; *o1 = x1;
}

struct FpsArgs  { int start[BB]; };
struct PermArgs { uint32_t sub[BB][2][2]; };  // [batch][round][subkey words]

// Scratch: selected indices per batch (FPS first, then random tail)
__device__ int g_idx[BB * MM];

// ---------------------------------------------------------------------------
// Host-side PRNG derivation — PARTITIONABLE threefry semantics (jax >= 0.4.36
// default):
//   split(key, n)[i]        = threefry(key, (0, i))      (both lanes = new key)
//   random_bits(key,32,shp) : element i -> threefry(key, (0, i)), value y0^y1
//   fold_in(key, d)         = threefry(key, seed(d))     (unchanged)
// ---------------------------------------------------------------------------
static void compute_consts(FpsArgs* fa, PermArgs* pa) {
  // base key = jax.random.key(42) -> (0, 42)
  for (int b = 0; b < BB; b++) {
    // fps_key[b] = split(key, 8)[b] = threefry(key, (0, b))
    uint32_t fk0, fk1;
    threefry2x32(0u, 42u, 0u, (uint32_t)b, &fk0, &fk1);
    // randint(fps_key, (), 0, 8192):
    //   k1, k2 = split(fps_key)  -> k2 = threefry(fps_key, (0,1))
    //   lower_bits = random_bits(k2, 32, ()) -> y0^y1 of threefry(k2,(0,0))
    //   span = 8192 (pow2) -> multiplier = 0 -> start = lower_bits % 8192
    uint32_t k20, k21;
    threefry2x32(fk0, fk1, 0u, 1u, &k20, &k21);
    uint32_t s0, s1;
    threefry2x32(k20, k21, 0u, 0u, &s0, &s1);
    fa->start[b] = (int)((s0 ^ s1) & (NN - 1));
  }
  // rkey = fold_in(key, 1) = threefry(key, threefry_seed(1)=(0,1))
  uint32_t rk0, rk1;
  threefry2x32(0u, 42u, 0u, 1u, &rk0, &rk1);
  for (int b = 0; b < BB; b++) {
    // rkeys[b] = split(rkey, 8)[b] = threefry(rkey, (0, b))
    uint32_t k0, k1;
    threefry2x32(rk0, rk1, 0u, (uint32_t)b, &k0, &k1);
    // permutation -> _shuffle: 2 rounds of {key,sub = split(key); bits(sub)}
    for (int r = 0; r < 2; r++) {
      uint32_t n0, n1, c0, c1;
      threefry2x32(k0, k1, 0u, 0u, &n0, &n1);  // new key  = split[0]
      threefry2x32(k0, k1, 0u, 1u, &c0, &c1);  // subkey   = split[1]
      pa->sub[b][r][0] = c0;
      pa->sub[b][r][1] = c1;
      k0 = n0; k1 = n1;
    }
  }
}

// ---------------------------------------------------------------------------
// FPS kernel: one block per batch, 1024 threads, 8 points/thread in registers
// ---------------------------------------------------------------------------
__global__ __launch_bounds__(1024, 1)
void fps_kernel(const float* __restrict__ pos, FpsArgs args) {
  const int b = blockIdx.x;
  const int tid = threadIdx.x;
  const float* px = pos + (size_t)b * 3 * NN;
  const float* py = px + NN;
  const float* pz = px + 2 * NN;

  float rx[8], ry[8], rz[8], rd[8];
#pragma unroll
  for (int j = 0; j < 8; j++) {
    int i = j * 1024 + tid;
    rx[j] = px[i]; ry[j] = py[i]; rz[j] = pz[i];
    rd[j] = 1e10f;
  }

  __shared__ float cx, cy, cz;
  __shared__ float swv[32];
  __shared__ int   swi[32];
  __shared__ int   s_widx;

  const int start = args.start[b];
  if (tid == 0) g_idx[b * MM] = start;
  if ((start & 1023) == tid) {
    int j = start >> 10;
#pragma unroll
    for (int jj = 0; jj < 8; jj++)
      if (jj == j) { cx = rx[jj]; cy = ry[jj]; cz = rz[jj]; }
  }
  __syncthreads();

  const int lane = tid & 31, warp = tid >> 5;

  for (int it = 1; it < FPS_M; ++it) {
    const float bx = cx, by = cy, bz = cz;
    float bestv = -1.0f;
    int   besti = 0;
#pragma unroll
    for (int j = 0; j < 8; j++) {
      float dx = __fsub_rn(rx[j], bx);
      float dy = __fsub_rn(ry[j], by);
      float dz = __fsub_rn(rz[j], bz);
      float dd = __fadd_rn(__fadd_rn(__fmul_rn(dx, dx), __fmul_rn(dy, dy)),
                           __fmul_rn(dz, dz));
      float nv = fminf(rd[j], dd);
      rd[j] = nv;
      int ii = j * 1024 + tid;
      if (nv > bestv) { bestv = nv; besti = ii; }
    }
    // warp reduce: max value, tie -> lower index (argmax semantics)
#pragma unroll
    for (int off = 16; off; off >>= 1) {
      float ov = __shfl_down_sync(0xffffffffu, bestv, off);
      int   oi = __shfl_down_sync(0xffffffffu, besti, off);
      if (ov > bestv || (ov == bestv && oi < besti)) { bestv = ov; besti = oi; }
    }
    if (lane == 0) { swv[warp] = bestv; swi[warp] = besti; }
    __syncthreads();
    if (warp == 0) {
      bestv = swv[lane]; besti = swi[lane];
#pragma unroll
      for (int off = 16; off; off >>= 1) {
        float ov = __shfl_down_sync(0xffffffffu, bestv, off);
        int   oi = __shfl_down_sync(0xffffffffu, besti, off);
        if (ov > bestv || (ov == bestv && oi < besti)) { bestv = ov; besti = oi; }
      }
      if (lane == 0) { s_widx = besti; g_idx[b * MM + it] = besti; }
    }
    __syncthreads();
    const int w = s_widx;
    if ((w & 1023) == tid) {
      int j = w >> 10;
#pragma unroll
      for (int jj = 0; jj < 8; jj++)
        if (jj == j) { cx = rx[jj]; cy = ry[jj]; cz = rz[jj]; }
    }
    __syncthreads();
  }
}

// ---------------------------------------------------------------------------
// Permutation kernel: 2 rounds of (threefry bits -> stable sort) per batch.
// Partitionable bits: element i -> y0 ^ y1 of threefry(subkey, (0, i)).
// Stable sort emulated by bitonic sort on packed u64: key<<32 | pos<<13 | val
// ---------------------------------------------------------------------------
__global__ __launch_bounds__(1024, 1)
void perm_kernel(PermArgs args) {
  extern __shared__ unsigned long long A[];  // NN entries = 64 KB
  const int b = blockIdx.x;
  const int tid = threadIdx.x;

  for (int r = 0; r < 2; ++r) {
    const uint32_t k0 = args.sub[b][r][0];
    const uint32_t k1 = args.sub[b][r][1];
    uint32_t keys[8];
#pragma unroll
    for (int t = 0; t < 8; ++t) {
      int i = tid + t * 1024;
      uint32_t y0, y1;
      threefry2x32(k0, k1, 0u, (uint32_t)i, &y0, &y1);
      keys[t] = y0 ^ y1;
    }
#pragma unroll
    for (int t = 0; t < 8; ++t) {
      int i = tid + t * 1024;
      uint32_t v = (r == 0) ? (uint32_t)i : (uint32_t)(A[i] & 0x1FFFull);
      A[i] = ((unsigned long long)keys[t] << 32) |
             ((unsigned long long)(uint32_t)i << 13) | v;
    }
    __syncthreads();
    // bitonic sort ascending over NN u64 entries
    for (int kk = 2; kk <= NN; kk <<= 1) {
      for (int jj = kk >> 1; jj > 0; jj >>= 1) {
#pragma unroll
        for (int t = 0; t < 8; ++t) {
          int i = tid + t * 1024;
          int ixj = i ^ jj;
          if (ixj > i) {
            bool up = ((i & kk) == 0);
            unsigned long long a = A[i], c = A[ixj];
            if ((a > c) == up) { A[i] = c; A[ixj] = a; }
          }
        }
        __syncthreads();
      }
    }
  }
  for (int t = tid; t < RAND_M; t += 1024)
    g_idx[b * MM + FPS_M + t] = (int)(A[t] & 0x1FFFull);
}

// ---------------------------------------------------------------------------
// KNN + softmax aggregation: thread-per-center, pos staged via shared tiles
// ---------------------------------------------------------------------------
__global__ __launch_bounds__(128, 4)
void knn_kernel(const float* __restrict__ x, const float* __restrict__ pos,
                float* __restrict__ out) {
  const int b  = blockIdx.x >> 4;
  const int ci = ((blockIdx.x & 15) << 7) + threadIdx.x;  // center 0..2047
  const float* px = pos + (size_t)b * 3 * NN;

  __shared__ float sax[2048], say[2048], saz[2048], ssn[2048];

  const int cidx = g_idx[b * MM + ci];
  const float sx = px[cidx], sy = px[NN + cidx], sz = px[2 * NN + cidx];
  const float sm = __fadd_rn(__fadd_rn(__fmul_rn(sx, sx), __fmul_rn(sy, sy)),
                             __fmul_rn(sz, sz));

  float kd[KNNK];
  int   ki[KNNK];
#pragma unroll
  for (int k = 0; k < KNNK; k++) { kd[k] = 3.4e38f; ki[k] = 0; }
  float worstv = 3.4e38f;
  int   worsti = 0, worsts = 0;

  for (int tile = 0; tile < 4; ++tile) {
    __syncthreads();
    const int base = tile * 2048;
    for (int t = threadIdx.x; t < 2048; t += 128) {
      float ax = px[base + t];
      float ay = px[NN + base + t];
      float az = px[2 * NN + base + t];
      sax[t] = ax; say[t] = ay; saz[t] = az;
      ssn[t] = __fadd_rn(__fadd_rn(__fmul_rn(ax, ax), __fmul_rn(ay, ay)),
                         __fmul_rn(az, az));
    }
    __syncthreads();
#pragma unroll 4
    for (int t = 0; t < 2048; ++t) {
      float dot = __fadd_rn(
          __fadd_rn(__fmul_rn(sx, sax[t]), __fmul_rn(sy, say[t])),
          __fmul_rn(sz, saz[t]));
      float d2 = __fsub_rn(__fadd_rn(sm, ssn[t]), __fmul_rn(2.0f, dot));
      if (d2 < worstv) {
        int gi = base + t;
        kd[worsts] = d2; ki[worsts] = gi;
        worstv = kd[0]; worsti = ki[0]; worsts = 0;
#pragma unroll
        for (int k = 1; k < KNNK; k++) {
          if (kd[k] > worstv || (kd[k] == worstv && ki[k] > worsti)) {
            worstv = kd[k]; worsti = ki[k]; worsts = k;
          }
        }
      }
    }
  }

  // softmax weights over exact euclidean distances (recomputed like reference)
  float w[KNNK];
  float maxl = -3.4e38f;
#pragma unroll
  for (int k = 0; k < KNNK; k++) {
    int id = ki[k];
    float dx = px[id] - sx, dy = px[NN + id] - sy, dz = px[2 * NN + id] - sz;
    float dn = sqrtf(dx * dx + dy * dy + dz * dz);
    dn = fmaxf(dn, 1e-6f);
    float l = -dn / 0.2f;
    w[k] = l;
    maxl = fmaxf(maxl, l);
  }
  float s = 0.0f;
#pragma unroll
  for (int k = 0; k < KNNK; k++) { w[k] = expf(w[k] - maxl); s += w[k]; }
  float inv = 1.0f / s;
#pragma unroll
  for (int k = 0; k < KNNK; k++) w[k] *= inv;

  // pos_sub output: [B][3][M] at offset B*C*M
  float* outpos = out + (size_t)BB * CC * MM;
  outpos[(size_t)b * 3 * MM + ci] = sx;
  outpos[(size_t)b * 3 * MM + MM + ci] = sy;
  outpos[(size_t)b * 3 * MM + 2 * MM + ci] = sz;

  // x_sub output: [B][C][M]
  const float* xb = x + (size_t)b * CC * NN;
#pragma unroll 2
  for (int c = 0; c < CC; ++c) {
    const float* row = xb + (size_t)c * NN;
    float acc = 0.0f;
#pragma unroll
    for (int k = 0; k < KNNK; k++) acc += w[k] * row[ki[k]];
    out[((size_t)b * CC + c) * MM + ci] = acc;
  }
}

// ---------------------------------------------------------------------------
extern "C" void kernel_launch(void* const* d_in, const int* in_sizes, int n_in,
                              void* d_out, int out_size) {
  const float* x   = (const float*)d_in[0];
  const float* pos = (const float*)d_in[1];
  (void)in_sizes; (void)n_in; (void)out_size;

  FpsArgs fa;
  PermArgs pa;
  compute_consts(&fa, &pa);

  cudaFuncSetAttribute(perm_kernel,
                       cudaFuncAttributeMaxDynamicSharedMemorySize, 65536);

  fps_kernel<<<BB, 1024>>>(pos, fa);
  perm_kernel<<<BB, 1024, 65536>>>(pa);
  knn_kernel<<<BB * 16, 128>>>(x, pos, (float*)d_out);
}

// round 5
// speedup vs baseline: 1.2885x; 1.2885x over previous
#include <cuda_runtime.h>
#include <cstdint>
#include <math.h>

// Problem constants (shapes are fixed by the dataset)
#define BB 8
#define CC 64
#define NN 8192
#define MM 2048
#define KNNK 16
#define FPS_M 1433   // int(2048 * 0.7)
#define RAND_M 615   // 2048 - 1433

// ---------------------------------------------------------------------------
// Threefry-2x32 core (jax threefry2x32 primitive)
// ---------------------------------------------------------------------------
__host__ __device__ __forceinline__ void threefry2x32(
    uint32_t k0, uint32_t k1, uint32_t c0, uint32_t c1,
    uint32_t* o0, uint32_t* o1) {
  uint32_t ks2 = 0x1BD11BDAu ^ k0 ^ k1;
  uint32_t x0 = c0 + k0;
  uint32_t x1 = c1 + k1;
#define TF_ROTL(v, r) (((v) << (r)) | ((v) >> (32 - (r))))
#define TF_ROUND(r) do { x0 += x1; x1 = TF_ROTL(x1, r); x1 ^= x0; } while (0)
  TF_ROUND(13); TF_ROUND(15); TF_ROUND(26); TF_ROUND(6);
  x0 += k1; x1 += ks2 + 1u;
  TF_ROUND(17); TF_ROUND(29); TF_ROUND(16); TF_ROUND(24);
  x0 += ks2; x1 += k0 + 2u;
  TF_ROUND(13); TF_ROUND(15); TF_ROUND(26); TF_ROUND(6);
  x0 += k0; x1 += k1 + 3u;
  TF_ROUND(17); TF_ROUND(29); TF_ROUND(16); TF_ROUND(24);
  x0 += k1; x1 += ks2 + 4u;
  TF_ROUND(13); TF_ROUND(15); TF_ROUND(26); TF_ROUND(6);
  x0 += ks2; x1 += k0 + 5u;
#undef TF_ROUND
#undef TF_ROTL
  *o0 = x0; *o1 = x1;
}

struct FpsArgs  { int start[BB]; };
struct PermArgs { uint32_t sub[BB][2][2]; };  // [batch][round][subkey words]

// Scratch: selected indices per batch (FPS first, then random tail)
__device__ int g_idx[BB * MM];

// ---------------------------------------------------------------------------
// Packed f32x2 helpers (bit-exact per-lane .rn semantics, sm_103a)
// ---------------------------------------------------------------------------
__device__ __forceinline__ unsigned long long f2_pack(float lo, float hi) {
  unsigned long long o;
  asm("mov.b64 %0, {%1, %2};" : "=l"(o) : "f"(lo), "f"(hi));
  return o;
}
__device__ __forceinline__ void f2_unpack(unsigned long long v, float* lo, float* hi) {
  asm("mov.b64 {%0, %1}, %2;" : "=f"(*lo), "=f"(*hi) : "l"(v));
}
__device__ __forceinline__ unsigned long long f2_add(unsigned long long a,
                                                     unsigned long long b) {
  unsigned long long o;
  asm("add.rn.f32x2 %0, %1, %2;" : "=l"(o) : "l"(a), "l"(b));
  return o;
}
__device__ __forceinline__ unsigned long long f2_mul(unsigned long long a,
                                                     unsigned long long b) {
  unsigned long long o;
  asm("mul.rn.f32x2 %0, %1, %2;" : "=l"(o) : "l"(a), "l"(b));
  return o;
}

// ---------------------------------------------------------------------------
// Host-side PRNG derivation — PARTITIONABLE threefry semantics:
//   split(key, n)[i]        = threefry(key, (0, i))
//   random_bits(key,32,shp) : element i -> threefry(key, (0, i)), value y0^y1
//   fold_in(key, d)         = threefry(key, (0, d))
// ---------------------------------------------------------------------------
static void compute_consts(FpsArgs* fa, PermArgs* pa) {
  for (int b = 0; b < BB; b++) {
    uint32_t fk0, fk1;
    threefry2x32(0u, 42u, 0u, (uint32_t)b, &fk0, &fk1);
    uint32_t k20, k21;
    threefry2x32(fk0, fk1, 0u, 1u, &k20, &k21);
    uint32_t s0, s1;
    threefry2x32(k20, k21, 0u, 0u, &s0, &s1);
    fa->start[b] = (int)((s0 ^ s1) & (NN - 1));
  }
  uint32_t rk0, rk1;
  threefry2x32(0u, 42u, 0u, 1u, &rk0, &rk1);
  for (int b = 0; b < BB; b++) {
    uint32_t k0, k1;
    threefry2x32(rk0, rk1, 0u, (uint32_t)b, &k0, &k1);
    for (int r = 0; r < 2; r++) {
      uint32_t n0, n1, c0, c1;
      threefry2x32(k0, k1, 0u, 0u, &n0, &n1);  // new key  = split[0]
      threefry2x32(k0, k1, 0u, 1u, &c0, &c1);  // subkey   = split[1]
      pa->sub[b][r][0] = c0;
      pa->sub[b][r][1] = c1;
      k0 = n0; k1 = n1;
    }
  }
}

// Fused FPS + permutation kernel. Blocks 0..7 = FPS(batch), 8..15 = perm(batch).
// Dynamic shared: FPS uses 3*NN floats (coord mirror) + 32 u64 partials + 1 int.
//                 Perm uses NN u64 sort buffer. max = 96KB + pad.
#define SMEM_FUSED (3 * NN * 4 + 32 * 8 + 64)

__global__ __launch_bounds__(1024, 1)
void fused_kernel(const float* __restrict__ pos, FpsArgs fargs, PermArgs pargs) {
  extern __shared__ char smem_raw[];
  const int tid = threadIdx.x;

  if (blockIdx.x < BB) {
    // ===================== FPS =====================
    const int b = blockIdx.x;
    float* sax = (float*)smem_raw;
    float* say = sax + NN;
    float* saz = say + NN;
    unsigned long long* swv = (unsigned long long*)(saz + NN);
    int* s_w = (int*)(swv + 32);

    const float* px = pos + (size_t)b * 3 * NN;
    const float* py = px + NN;
    const float* pz = px + 2 * NN;

    // coords in registers as f32x2 pairs (points 2j*1024+tid, (2j+1)*1024+tid)
    unsigned long long rx2[4], ry2[4], rz2[4];
    float rd[8];
#pragma unroll
    for (int j = 0; j < 4; j++) {
      int i0 = (2 * j) * 1024 + tid;
      int i1 = i0 + 1024;
      float x0 = px[i0], x1 = px[i1];
      float y0 = py[i0], y1 = py[i1];
      float z0 = pz[i0], z1 = pz[i1];
      rx2[j] = f2_pack(x0, x1);
      ry2[j] = f2_pack(y0, y1);
      rz2[j] = f2_pack(z0, z1);
      sax[i0] = x0; sax[i1] = x1;
      say[i0] = y0; say[i1] = y1;
      saz[i0] = z0; saz[i1] = z1;
      rd[2 * j] = 1e10f; rd[2 * j + 1] = 1e10f;
    }
    __syncthreads();

    const int start = fargs.start[b];
    if (tid == 0) g_idx[b * MM] = start;
    float bx = sax[start], by = say[start], bz = saz[start];

    const int lane = tid & 31, warp = tid >> 5;

    for (int it = 1; it < FPS_M; ++it) {
      // negated center, packed (exact sign flip)
      unsigned long long nbx2 = f2_pack(-bx, -bx);
      unsigned long long nby2 = f2_pack(-by, -by);
      unsigned long long nbz2 = f2_pack(-bz, -bz);

      float bestv = -1.0f;
      int   besti = 0;
#pragma unroll
      for (int j = 0; j < 4; j++) {
        unsigned long long dx2 = f2_add(rx2[j], nbx2);
        unsigned long long dy2 = f2_add(ry2[j], nby2);
        unsigned long long dz2 = f2_add(rz2[j], nbz2);
        unsigned long long dd2 =
            f2_add(f2_add(f2_mul(dx2, dx2), f2_mul(dy2, dy2)), f2_mul(dz2, dz2));
        float d0, d1;
        f2_unpack(dd2, &d0, &d1);
        float nv0 = fminf(rd[2 * j], d0);
        rd[2 * j] = nv0;
        if (nv0 > bestv) { bestv = nv0; besti = (2 * j) * 1024 + tid; }
        float nv1 = fminf(rd[2 * j + 1], d1);
        rd[2 * j + 1] = nv1;
        if (nv1 > bestv) { bestv = nv1; besti = (2 * j + 1) * 1024 + tid; }
      }
      // pack (value, index) -> u64 key; dist >= 0 so bits are monotone.
      // (NN - idx) makes equal values prefer the LOWER index under max.
      unsigned long long key =
          ((unsigned long long)__float_as_uint(bestv) << 32) |
          (unsigned long long)(uint32_t)(NN - besti);
#pragma unroll
      for (int off = 16; off; off >>= 1) {
        unsigned long long o = __shfl_down_sync(0xffffffffu, key, off);
        key = (o > key) ? o : key;
      }
      if (lane == 0) swv[warp] = key;
      __syncthreads();
      if (warp == 0) {
        unsigned long long k = swv[lane];
#pragma unroll
        for (int off = 16; off; off >>= 1) {
          unsigned long long o = __shfl_down_sync(0xffffffffu, k, off);
          k = (o > k) ? o : k;
        }
        if (lane == 0) {
          int w = NN - (int)(k & 0xFFFFu);
          s_w[0] = w;
          g_idx[b * MM + it] = w;
        }
      }
      __syncthreads();
      const int w = s_w[0];
      bx = sax[w]; by = say[w]; bz = saz[w];
    }
  } else {
    // ===================== random-permutation tail =====================
    const int b = blockIdx.x - BB;
    unsigned long long* A = (unsigned long long*)smem_raw;  // NN entries

    for (int r = 0; r < 2; ++r) {
      const uint32_t k0 = pargs.sub[b][r][0];
      const uint32_t k1 = pargs.sub[b][r][1];
      uint32_t keys[8];
#pragma unroll
      for (int t = 0; t < 8; ++t) {
        int i = tid + t * 1024;
        uint32_t y0, y1;
        threefry2x32(k0, k1, 0u, (uint32_t)i, &y0, &y1);
        keys[t] = y0 ^ y1;
      }
#pragma unroll
      for (int t = 0; t < 8; ++t) {
        int i = tid + t * 1024;
        uint32_t v = (r == 0) ? (uint32_t)i : (uint32_t)(A[i] & 0x1FFFull);
        A[i] = ((unsigned long long)keys[t] << 32) |
               ((unsigned long long)(uint32_t)i << 13) | v;
      }
      __syncthreads();
      // bitonic sort ascending over NN u64 entries (stable via pos field)
      for (int kk = 2; kk <= NN; kk <<= 1) {
        for (int jj = kk >> 1; jj > 0; jj >>= 1) {
#pragma unroll
          for (int t = 0; t < 8; ++t) {
            int i = tid + t * 1024;
            int ixj = i ^ jj;
            if (ixj > i) {
              bool up = ((i & kk) == 0);
              unsigned long long a = A[i], c = A[ixj];
              if ((a > c) == up) { A[i] = c; A[ixj] = a; }
            }
          }
          __syncthreads();
        }
      }
    }
    for (int t = tid; t < RAND_M; t += 1024)
      g_idx[b * MM + FPS_M + t] = (int)(A[t] & 0x1FFFull);
  }
}

// ---------------------------------------------------------------------------
// KNN + softmax aggregation: thread-per-center, pos staged via shared tiles
// ---------------------------------------------------------------------------
__global__ __launch_bounds__(128, 4)
void knn_kernel(const float* __restrict__ x, const float* __restrict__ pos,
                float* __restrict__ out) {
  const int b  = blockIdx.x >> 4;
  const int ci = ((blockIdx.x & 15) << 7) + threadIdx.x;  // center 0..2047
  const float* px = pos + (size_t)b * 3 * NN;

  __shared__ float sax[2048], say[2048], saz[2048], ssn[2048];

  const int cidx = g_idx[b * MM + ci];
  const float sx = px[cidx], sy = px[NN + cidx], sz = px[2 * NN + cidx];
  const float sm = __fadd_rn(__fadd_rn(__fmul_rn(sx, sx), __fmul_rn(sy, sy)),
                             __fmul_rn(sz, sz));

  float kd[KNNK];
  int   ki[KNNK];
#pragma unroll
  for (int k = 0; k < KNNK; k++) { kd[k] = 3.4e38f; ki[k] = 0; }
  float worstv = 3.4e38f;
  int   worsti = 0, worsts = 0;

  for (int tile = 0; tile < 4; ++tile) {
    __syncthreads();
    const int base = tile * 2048;
    for (int t = threadIdx.x; t < 2048; t += 128) {
      float ax = px[base + t];
      float ay = px[NN + base + t];
      float az = px[2 * NN + base + t];
      sax[t] = ax; say[t] = ay; saz[t] = az;
      ssn[t] = __fadd_rn(__fadd_rn(__fmul_rn(ax, ax), __fmul_rn(ay, ay)),
                         __fmul_rn(az, az));
    }
    __syncthreads();
#pragma unroll 4
    for (int t = 0; t < 2048; ++t) {
      float dot = __fadd_rn(
          __fadd_rn(__fmul_rn(sx, sax[t]), __fmul_rn(sy, say[t])),
          __fmul_rn(sz, saz[t]));
      float d2 = __fsub_rn(__fadd_rn(sm, ssn[t]), __fmul_rn(2.0f, dot));
      if (d2 < worstv) {
        int gi = base + t;
        kd[worsts] = d2; ki[worsts] = gi;
        worstv = kd[0]; worsti = ki[0]; worsts = 0;
#pragma unroll
        for (int k = 1; k < KNNK; k++) {
          if (kd[k] > worstv || (kd[k] == worstv && ki[k] > worsti)) {
            worstv = kd[k]; worsti = ki[k]; worsts = k;
          }
        }
      }
    }
  }

  // softmax weights over exact euclidean distances (recomputed like reference)
  float w[KNNK];
  float maxl = -3.4e38f;
#pragma unroll
  for (int k = 0; k < KNNK; k++) {
    int id = ki[k];
    float dx = px[id] - sx, dy = px[NN + id] - sy, dz = px[2 * NN + id] - sz;
    float dn = sqrtf(dx * dx + dy * dy + dz * dz);
    dn = fmaxf(dn, 1e-6f);
    float l = -dn / 0.2f;
    w[k] = l;
    maxl = fmaxf(maxl, l);
  }
  float s = 0.0f;
#pragma unroll
  for (int k = 0; k < KNNK; k++) { w[k] = expf(w[k] - maxl); s += w[k]; }
  float inv = 1.0f / s;
#pragma unroll
  for (int k = 0; k < KNNK; k++) w[k] *= inv;

  // pos_sub output: [B][3][M] at offset B*C*M
  float* outpos = out + (size_t)BB * CC * MM;
  outpos[(size_t)b * 3 * MM + ci] = sx;
  outpos[(size_t)b * 3 * MM + MM + ci] = sy;
  outpos[(size_t)b * 3 * MM + 2 * MM + ci] = sz;

  // x_sub output: [B][C][M]
  const float* xb = x + (size_t)b * CC * NN;
#pragma unroll 2
  for (int c = 0; c < CC; ++c) {
    const float* row = xb + (size_t)c * NN;
    float acc = 0.0f;
#pragma unroll
    for (int k = 0; k < KNNK; k++) acc += w[k] * row[ki[k]];
    out[((size_t)b * CC + c) * MM + ci] = acc;
  }
}

// ---------------------------------------------------------------------------
extern "C" void kernel_launch(void* const* d_in, const int* in_sizes, int n_in,
                              void* d_out, int out_size) {
  const float* x   = (const float*)d_in[0];
  const float* pos = (const float*)d_in[1];
  (void)in_sizes; (void)n_in; (void)out_size;

  FpsArgs fa;
  PermArgs pa;
  compute_consts(&fa, &pa);

  cudaFuncSetAttribute(fused_kernel,
                       cudaFuncAttributeMaxDynamicSharedMemorySize, SMEM_FUSED);

  fused_kernel<<<2 * BB, 1024, SMEM_FUSED>>>(pos, fa, pa);
  knn_kernel<<<BB * 16, 128>>>(x, pos, (float*)d_out);
}